// round 8
// baseline (speedup 1.0000x reference)
#include <cuda_runtime.h>
#include <stdint.h>

#define IN_W 256
#define IN_HW 65536
#define OUT_W 254

#define R_OUT 6            // output rows per CTA (= 6 warps, 1 row each)
#define ROWS_IN 8          // R_OUT + 2
#define POS 130            // 128 + 2 halo input positions
#define ROW_W 2080         // POS * 16 words per input row
#define A_WORDS (ROWS_IN * ROW_W)        // 16640
#define BF_WORDS 2304                    // 3 ky * 6 ks * 2 h * 32 lanes * 2 regs
#define SMEM_BYTES ((A_WORDS + BF_WORDS + 16) * 4)   // 75,840 B -> 2 CTAs/SM
#define NTHREADS 192

// word-index swizzle: XOR bits[5:7) into bits[2:4) (proven conflict-free for
// LDS.32 fragment loads and the STS.128 transpose stores)
__device__ __forceinline__ uint32_t swzw(uint32_t w) {
    return w ^ (((w >> 5) & 3u) << 2);
}
__device__ __forceinline__ uint32_t tf32r(float f) {
    uint32_t r; asm("cvt.rna.tf32.f32 %0, %1;" : "=r"(r) : "f"(f)); return r;
}
__device__ __forceinline__ void mma_tf32(float c[4], uint32_t a0, uint32_t a1,
                                         uint32_t a2, uint32_t a3,
                                         uint32_t b0, uint32_t b1) {
    asm("mma.sync.aligned.m16n8k8.row.col.f32.tf32.tf32.f32 "
        "{%0,%1,%2,%3}, {%4,%5,%6,%7}, {%8,%9}, {%0,%1,%2,%3};"
        : "+f"(c[0]), "+f"(c[1]), "+f"(c[2]), "+f"(c[3])
        : "r"(a0), "r"(a1), "r"(a2), "r"(a3), "r"(b0), "r"(b1));
}
__device__ __forceinline__ float mish_f(float v) {
    if (v > 30.0f) return v;
    float e  = __expf(v);
    float t  = 1.0f + e;
    float t2 = t * t;
    return v * __fdividef(t2 - 1.0f, t2 + 1.0f);
}

__global__ __launch_bounds__(NTHREADS, 2)
void conv_tc_kernel(const float* __restrict__ x,
                    const float* __restrict__ w,
                    const float* __restrict__ bias,
                    float* __restrict__ y)
{
    extern __shared__ uint32_t sm[];
    uint32_t* Asm = sm;                     // [row][pos][ci16], swizzled tf32
    uint32_t* Bf  = sm + A_WORDS;           // lane-ordered B fragments
    float*    bsm = (float*)(sm + A_WORDS + BF_WORDS);

    const int tid  = threadIdx.x;
    const int wid  = tid >> 5;
    const int lane = tid & 31;
    const int lm   = lane >> 2;
    const int lk   = lane & 3;
    const int X0   = blockIdx.x * 128;
    const int Y0   = blockIdx.y * R_OUT;
    const int n    = blockIdx.z;

    if (tid < 16) bsm[tid] = bias[tid];

    // ---- B fragments: Bf[(ky*6+ks)*128 + h*64 + lane*2 + reg]
    for (int i = tid; i < BF_WORDS; i += NTHREADS) {
        int reg = i & 1;
        int ln  = (i >> 1) & 31;
        int h   = (i >> 6) & 1;
        int t   = i >> 7;              // ky*6+ks
        int ks  = t % 6, ky = t / 6;
        int k   = ks * 8 + (ln & 3) + reg * 4;
        int co  = h * 8 + (ln >> 2);
        int kx  = k >> 4, ci = k & 15;
        Bf[i] = tf32r(w[(co * 16 + ci) * 9 + ky * 3 + kx]);
    }

    // ---- input transpose: NCHW -> smem [row][pos][ci], tf32, swizzled
    const float* xn = x + (size_t)n * 16 * IN_HW;
    for (int i = tid; i < ROWS_IN * POS; i += NTHREADS) {
        int pos = i % POS;
        int row = i / POS;
        int gy = Y0 + row; if (gy > 255) gy = 255;   // clamped rows feed guarded outputs only
        int gx = X0 + pos; if (gx > 255) gx = 255;
        const float* src = xn + gy * IN_W + gx;
        uint32_t wb = row * ROW_W + pos * 16;
        #pragma unroll
        for (int c4 = 0; c4 < 4; c4++) {
            uint4 q;
            q.x = tf32r(src[(size_t)(c4 * 4 + 0) * IN_HW]);
            q.y = tf32r(src[(size_t)(c4 * 4 + 1) * IN_HW]);
            q.z = tf32r(src[(size_t)(c4 * 4 + 2) * IN_HW]);
            q.w = tf32r(src[(size_t)(c4 * 4 + 3) * IN_HW]);
            *(uint4*)(Asm + swzw(wb + c4 * 4)) = q;
        }
    }
    __syncthreads();

    // ---- hoist ALL B fragments into registers (reused across the whole t loop)
    uint2 breg[3][6][2];
    #pragma unroll
    for (int ky = 0; ky < 3; ky++)
        #pragma unroll
        for (int ks = 0; ks < 6; ks++) {
            const uint32_t* bp = Bf + (ky * 6 + ks) * 128 + lane * 2;
            breg[ky][ks][0] = *(const uint2*)bp;
            breg[ky][ks][1] = *(const uint2*)(bp + 64);
        }

    // ---- mainloop: warp wid -> output row Y0+wid; 4 iters x 2 tiles (32 x's)
    const int r  = wid;
    const int yo = Y0 + r;

    #pragma unroll 1
    for (int t = 0; t < 4; t++) {
        const int posbase = t * 32;
        float c[2][2][4];           // [tile][n-half][regs] : 4 independent chains
        #pragma unroll
        for (int u = 0; u < 2; u++)
            #pragma unroll
            for (int h = 0; h < 2; h++)
                #pragma unroll
                for (int e = 0; e < 4; e++) c[u][h][e] = 0.f;

        #pragma unroll
        for (int ky = 0; ky < 3; ky++) {
            const uint32_t rb = (uint32_t)((r + ky) * ROW_W + (posbase + lm) * 16 + lk);
            #pragma unroll
            for (int ks = 0; ks < 6; ks++) {
                uint32_t sw  = swzw(rb + ks * 8);   // tile1 = +256 (swizzle-invariant)
                uint32_t sw4 = sw ^ 4u;
                uint2 b0 = breg[ky][ks][0];
                uint2 b1 = breg[ky][ks][1];
                uint32_t a0 = Asm[sw];
                uint32_t a1 = Asm[sw + 128];
                uint32_t a2 = Asm[sw4];
                uint32_t a3 = Asm[sw4 + 128];
                mma_tf32(c[0][0], a0, a1, a2, a3, b0.x, b0.y);
                mma_tf32(c[0][1], a0, a1, a2, a3, b1.x, b1.y);
                uint32_t a4 = Asm[sw + 256];
                uint32_t a5 = Asm[sw + 384];
                uint32_t a6 = Asm[sw4 + 256];
                uint32_t a7 = Asm[sw4 + 384];
                mma_tf32(c[1][0], a4, a5, a6, a7, b0.x, b0.y);
                mma_tf32(c[1][1], a4, a5, a6, a7, b1.x, b1.y);
            }
        }

        if (yo < OUT_W) {
            float* yn = y + ((size_t)n * 16) * (OUT_W * OUT_W) + (size_t)yo * OUT_W;
            #pragma unroll
            for (int u = 0; u < 2; u++) {
                int xoA = X0 + posbase + u * 16 + lm;
                int xoB = xoA + 8;
                #pragma unroll
                for (int h = 0; h < 2; h++) {
                    const float* cc = c[u][h];
                    int coA = h * 8 + lk * 2;
                    float bA = bsm[coA]     - 0.7f;
                    float bB = bsm[coA + 1] - 0.7f;
                    if (xoA < OUT_W) {
                        yn[(size_t)coA       * (OUT_W * OUT_W) + xoA] = mish_f(cc[0] + bA);
                        yn[(size_t)(coA + 1) * (OUT_W * OUT_W) + xoA] = mish_f(cc[1] + bB);
                    }
                    if (xoB < OUT_W) {
                        yn[(size_t)coA       * (OUT_W * OUT_W) + xoB] = mish_f(cc[2] + bA);
                        yn[(size_t)(coA + 1) * (OUT_W * OUT_W) + xoB] = mish_f(cc[3] + bB);
                    }
                }
            }
        }
    }
}

extern "C" void kernel_launch(void* const* d_in, const int* in_sizes, int n_in,
                              void* d_out, int out_size)
{
    const float* x  = (const float*)d_in[0];
    const float* w  = (const float*)d_in[1];
    const float* b  = (const float*)d_in[2];
    float* y = (float*)d_out;

    cudaFuncSetAttribute(conv_tc_kernel,
                         cudaFuncAttributeMaxDynamicSharedMemorySize, SMEM_BYTES);

    int N = in_sizes[0] / (16 * IN_HW);                 // 32
    dim3 grid(2, (OUT_W + R_OUT - 1) / R_OUT, N);       // 2 x 43 x 32
    conv_tc_kernel<<<grid, NTHREADS, SMEM_BYTES>>>(x, w, b, y);
}

// round 9
// speedup vs baseline: 1.3755x; 1.3755x over previous
#include <cuda_runtime.h>
#include <stdint.h>

#define IN_W 256
#define IN_HW 65536
#define OUT_W 254

#define R_SUB 4                 // output rows per subtile
#define ROWS_SUB 6              // input rows per subtile
#define PITCH 132               // words per input row slice (128+2 halo, +2 pad)
#define PLANE (ROWS_SUB * PITCH)        // 792 words per ci
#define BUFW (16 * PLANE)               // 12672 words per stage buffer
#define NCHUNK (16 * ROWS_SUB * 33)     // 3168 16B-chunks per subtile
#define BF_WORDS 2304                   // 3 ky * 6 ks * 2 h * 32 lanes * 2 regs
#define SMEM_BYTES ((2 * BUFW + BF_WORDS + 16) * 4)   // 110,656 B -> 2 CTAs/SM

__device__ __forceinline__ uint32_t tf32r(float f) {
    uint32_t r; asm("cvt.rna.tf32.f32 %0, %1;" : "=r"(r) : "f"(f)); return r;
}
__device__ __forceinline__ void mma_tf32(float c[4], uint32_t a0, uint32_t a1,
                                         uint32_t a2, uint32_t a3,
                                         uint32_t b0, uint32_t b1) {
    asm("mma.sync.aligned.m16n8k8.row.col.f32.tf32.tf32.f32 "
        "{%0,%1,%2,%3}, {%4,%5,%6,%7}, {%8,%9}, {%0,%1,%2,%3};"
        : "+f"(c[0]), "+f"(c[1]), "+f"(c[2]), "+f"(c[3])
        : "r"(a0), "r"(a1), "r"(a2), "r"(a3), "r"(b0), "r"(b1));
}
__device__ __forceinline__ float mish_f(float v) {
    if (v > 30.0f) return v;
    float e  = __expf(v);
    float t  = 1.0f + e;
    float t2 = t * t;
    return v * __fdividef(t2 - 1.0f, t2 + 1.0f);
}

__global__ __launch_bounds__(256, 2)
void conv_tc_kernel(const float* __restrict__ x,
                    const float* __restrict__ w,
                    const float* __restrict__ bias,
                    float* __restrict__ y)
{
    extern __shared__ uint32_t sm[];
    uint32_t* stage = sm;                    // 2 raw-layout stage buffers [ci][row][pos]
    uint32_t* Bf    = sm + 2 * BUFW;         // lane-ordered B fragments (tf32-rounded)
    float*    bsm   = (float*)(sm + 2 * BUFW + BF_WORDS);

    const int tid  = threadIdx.x;
    const int wid  = tid >> 5;
    const int lane = tid & 31;
    const int lm   = lane >> 2;
    const int lk   = lane & 3;
    const int X0   = blockIdx.x * 128;
    const int Y0   = blockIdx.y * 16;        // 16 output rows per CTA (4 subtiles)
    const int n    = blockIdx.z;

    if (tid < 16) bsm[tid] = bias[tid];

    // ---- B fragments: Bf[(ky*6+ks)*128 + h*64 + lane*2 + reg], rna-rounded tf32
    for (int i = tid; i < BF_WORDS; i += 256) {
        int reg = i & 1;
        int ln  = (i >> 1) & 31;
        int h   = (i >> 6) & 1;
        int t   = i >> 7;              // ky*6+ks
        int ks  = t % 6, ky = t / 6;
        int k   = ks * 8 + (ln & 3) + reg * 4;
        int co  = h * 8 + (ln >> 2);
        int kx  = k >> 4, ci = k & 15;
        Bf[i] = tf32r(w[(co * 16 + ci) * 9 + ky * 3 + kx]);
    }

    const float* xn = x + (size_t)n * 16 * IN_HW;
    const uint32_t sb = (uint32_t)__cvta_generic_to_shared(stage);

    // ---- async loader: subtile s (input rows Y0+4s .. +5) into stage buffer p, raw fp32
    #define LOAD_SUB(p, s)                                                          \
    do {                                                                            \
        int Ys = Y0 + 4 * (s);                                                      \
        for (int i = tid; i < NCHUNK; i += 256) {                                   \
            int pos16 = i % 33;                                                     \
            int rc    = i / 33;                                                     \
            int row   = rc % 6;                                                     \
            int ci    = rc / 6;                                                     \
            int gy = Ys + row; if (gy > 255) gy = 255;      /* dummy: guarded */    \
            int gx = X0 + pos16 * 4; if (gx > 252) gx = 252; /* dummy: guarded */   \
            const float* src = xn + (size_t)ci * IN_HW + gy * IN_W + gx;            \
            uint32_t dst = sb + (uint32_t)(((p) * BUFW + ci * PLANE + row * PITCH   \
                                            + pos16 * 4) * 4);                      \
            asm volatile("cp.async.cg.shared.global [%0], [%1], 16;"                \
                         :: "r"(dst), "l"(src));                                    \
        }                                                                           \
        asm volatile("cp.async.commit_group;");                                     \
    } while (0)

    LOAD_SUB(0, 0);
    LOAD_SUB(1, 1);

    const int rr  = wid >> 1;          // warp's output row within subtile (0..3)
    const int xh  = (wid & 1) * 64;    // warp's x half
    const int tb0 = lk * PLANE + lm;   // thread base offset

    #pragma unroll 1
    for (int s = 0; s < 4; s++) {
        if (s < 3) asm volatile("cp.async.wait_group 1;");
        else       asm volatile("cp.async.wait_group 0;");
        __syncthreads();

        const uint32_t* Ab = stage + (s & 1) * BUFW;
        const int yo = Y0 + 4 * s + rr;

        #pragma unroll 1
        for (int t = 0; t < 2; t++) {
            const int posbase = xh + t * 32;
            float c[2][2][4];          // [tile][n-half][regs]: 4 independent chains
            #pragma unroll
            for (int u = 0; u < 2; u++)
                #pragma unroll
                for (int h = 0; h < 2; h++)
                    #pragma unroll
                    for (int e = 0; e < 4; e++) c[u][h][e] = 0.f;

            #pragma unroll
            for (int ky = 0; ky < 3; ky++) {
                const uint32_t* ap = Ab + tb0 + (rr + ky) * PITCH + posbase;
                const uint32_t* bp = Bf + ky * 6 * 128 + lane * 2;
                #pragma unroll
                for (int ks = 0; ks < 6; ks++) {
                    // raw-layout fragment: ci plane = (ks&1)*8 + lk (+4), pos += kx
                    const uint32_t* a = ap + (ks & 1) * (8 * PLANE) + (ks >> 1);
                    uint2 b0 = *(const uint2*)(bp + ks * 128);
                    uint2 b1 = *(const uint2*)(bp + ks * 128 + 64);
                    uint32_t a0 = a[0];
                    uint32_t a1 = a[8];
                    uint32_t a2 = a[4 * PLANE];
                    uint32_t a3 = a[4 * PLANE + 8];
                    mma_tf32(c[0][0], a0, a1, a2, a3, b0.x, b0.y);
                    mma_tf32(c[0][1], a0, a1, a2, a3, b1.x, b1.y);
                    uint32_t a4 = a[16];
                    uint32_t a5 = a[24];
                    uint32_t a6 = a[4 * PLANE + 16];
                    uint32_t a7 = a[4 * PLANE + 24];
                    mma_tf32(c[1][0], a4, a5, a6, a7, b0.x, b0.y);
                    mma_tf32(c[1][1], a4, a5, a6, a7, b1.x, b1.y);
                }
            }

            if (yo < OUT_W) {
                float* yn = y + ((size_t)n * 16) * (OUT_W * OUT_W) + (size_t)yo * OUT_W;
                #pragma unroll
                for (int u = 0; u < 2; u++) {
                    int xoA = X0 + posbase + u * 16 + lm;
                    int xoB = xoA + 8;
                    #pragma unroll
                    for (int h = 0; h < 2; h++) {
                        const float* cc = c[u][h];
                        int coA = h * 8 + lk * 2;
                        float bA = bsm[coA]     - 0.7f;
                        float bB = bsm[coA + 1] - 0.7f;
                        if (xoA < OUT_W) {
                            yn[(size_t)coA       * (OUT_W * OUT_W) + xoA] = mish_f(cc[0] + bA);
                            yn[(size_t)(coA + 1) * (OUT_W * OUT_W) + xoA] = mish_f(cc[1] + bB);
                        }
                        if (xoB < OUT_W) {
                            yn[(size_t)coA       * (OUT_W * OUT_W) + xoB] = mish_f(cc[2] + bA);
                            yn[(size_t)(coA + 1) * (OUT_W * OUT_W) + xoB] = mish_f(cc[3] + bB);
                        }
                    }
                }
            }
        }

        __syncthreads();               // buffer (s&1) free before refill
        if (s < 2) LOAD_SUB(s & 1, s + 2);
    }
}

extern "C" void kernel_launch(void* const* d_in, const int* in_sizes, int n_in,
                              void* d_out, int out_size)
{
    const float* x  = (const float*)d_in[0];
    const float* w  = (const float*)d_in[1];
    const float* b  = (const float*)d_in[2];
    float* y = (float*)d_out;

    cudaFuncSetAttribute(conv_tc_kernel,
                         cudaFuncAttributeMaxDynamicSharedMemorySize, SMEM_BYTES);

    int N = in_sizes[0] / (16 * IN_HW);                 // 32
    dim3 grid(2, 16, N);                                // 2 x 16 x 32 = 1024 CTAs
    conv_tc_kernel<<<grid, 256, SMEM_BYTES>>>(x, w, b, y);
}

// round 10
// speedup vs baseline: 1.4619x; 1.0628x over previous
#include <cuda_runtime.h>
#include <stdint.h>

#define IN_W 256
#define IN_HW 65536
#define OUT_W 254

#define PITCH 68                 // words per staged row (64 + 2 halo + pad), %4==0
#define PLANE 408                // 6*PITCH; %32==24 -> lk*PLANE banks {0,24,16,8}: conflict-free
#define BUFW (8 * PLANE)         // 3264 words: 8 ci-planes per stage
#define NCHUNK (8 * 6 * 17)      // 816 16B cp.async chunks per phase
#define BF_WORDS 2304            // 18 ksteps * 128 lane-ordered words
#define SMEM_BYTES ((2 * BUFW + BF_WORDS + 16) * 4)   // 35,392 B -> 3 CTAs/SM

__device__ __forceinline__ uint32_t tf32r(float f) {
    uint32_t r; asm("cvt.rna.tf32.f32 %0, %1;" : "=r"(r) : "f"(f)); return r;
}
__device__ __forceinline__ void mma_tf32(float c[4], uint32_t a0, uint32_t a1,
                                         uint32_t a2, uint32_t a3,
                                         uint32_t b0, uint32_t b1) {
    asm("mma.sync.aligned.m16n8k8.row.col.f32.tf32.tf32.f32 "
        "{%0,%1,%2,%3}, {%4,%5,%6,%7}, {%8,%9}, {%0,%1,%2,%3};"
        : "+f"(c[0]), "+f"(c[1]), "+f"(c[2]), "+f"(c[3])
        : "r"(a0), "r"(a1), "r"(a2), "r"(a3), "r"(b0), "r"(b1));
}
__device__ __forceinline__ float mish_f(float v) {
    if (v > 30.0f) return v;
    float e  = __expf(v);
    float t  = 1.0f + e;
    float t2 = t * t;
    return v * __fdividef(t2 - 1.0f, t2 + 1.0f);
}

__global__ __launch_bounds__(256, 3)
void conv_tc_kernel(const float* __restrict__ x,
                    const float* __restrict__ w,
                    const float* __restrict__ bias,
                    float* __restrict__ y)
{
    extern __shared__ uint32_t sm[];
    uint32_t* stage = sm;                    // 2 half-K stage buffers [ci8][row6][pos68]
    uint32_t* Bf    = sm + 2 * BUFW;         // lane-ordered B fragments (tf32)
    float*    bsm   = (float*)(sm + 2 * BUFW + BF_WORDS);

    const int tid  = threadIdx.x;
    const int wid  = tid >> 5;
    const int lane = tid & 31;
    const int lm   = lane >> 2;
    const int lk   = lane & 3;
    const int X0   = blockIdx.x * 64;
    const int Y0   = blockIdx.y * 16;        // 16 output rows per CTA (4 subtiles of 4)
    const int n    = blockIdx.z;

    if (tid < 16) bsm[tid] = bias[tid];

    // ---- B fragments: Bf[(kc*9 + ky*3 + kx)*128 + h*64 + lane*2 + reg]
    for (int i = tid; i < BF_WORDS; i += 256) {
        int reg = i & 1;
        int ln  = (i >> 1) & 31;
        int h   = (i >> 6) & 1;
        int t   = i >> 7;                    // kc*9 + ky*3 + kx
        int kx  = t % 3;
        int kyc = t / 3;
        int ky  = kyc % 3;
        int kc  = kyc / 3;
        int ci  = kc * 8 + (ln & 3) + reg * 4;
        int co  = h * 8 + (ln >> 2);
        Bf[i] = tf32r(w[(co * 16 + ci) * 9 + ky * 3 + kx]);
    }

    const float* xn = x + (size_t)n * 16 * IN_HW;
    const uint32_t sb = (uint32_t)__cvta_generic_to_shared(stage);

    // ---- async loader: phase ph = subtile (ph>>1), ci-half (ph&1) -> buffer p
    #define LOAD_PH(p, ph)                                                          \
    do {                                                                            \
        int Ys  = Y0 + 4 * ((ph) >> 1);                                             \
        int cib = ((ph) & 1) * 8;                                                   \
        for (int i = tid; i < NCHUNK; i += 256) {                                   \
            int pos16 = i % 17;                                                     \
            int rc    = i / 17;                                                     \
            int row   = rc % 6;                                                     \
            int cil   = rc / 6;                                                     \
            int gy = Ys + row; if (gy > 255) gy = 255;       /* dummy: guarded */   \
            int gx = X0 + pos16 * 4; if (gx > 252) gx = 252; /* dummy: guarded */   \
            const float* src = xn + (size_t)(cib + cil) * IN_HW + gy * IN_W + gx;   \
            uint32_t dst = sb + (uint32_t)(((p) * BUFW + cil * PLANE               \
                                            + row * PITCH + pos16 * 4) * 4);        \
            asm volatile("cp.async.cg.shared.global [%0], [%1], 16;"                \
                         :: "r"(dst), "l"(src));                                    \
        }                                                                           \
        asm volatile("cp.async.commit_group;");                                     \
    } while (0)

    LOAD_PH(0, 0);
    LOAD_PH(1, 1);

    const int rr = wid >> 1;             // warp's row within subtile (0..3)
    const int q  = (wid & 1) * 32;       // warp's 32-pos quarter
    float c[2][2][4];                    // [tile16][n-half][regs], persists across kc pair

    #pragma unroll 1
    for (int ph = 0; ph < 8; ph++) {
        if (ph < 7) asm volatile("cp.async.wait_group 1;");
        else        asm volatile("cp.async.wait_group 0;");
        __syncthreads();

        const int kc = ph & 1;
        const uint32_t* Ab = stage + kc * BUFW;   // buffer index == kc parity

        if (kc == 0) {
            #pragma unroll
            for (int u = 0; u < 2; u++)
                #pragma unroll
                for (int h = 0; h < 2; h++)
                    #pragma unroll
                    for (int e = 0; e < 4; e++) c[u][h][e] = 0.f;
        }

        #pragma unroll
        for (int ky = 0; ky < 3; ky++) {
            const uint32_t* ap = Ab + lk * PLANE + (rr + ky) * PITCH + q + lm;
            const uint32_t* bp = Bf + (kc * 9 + ky * 3) * 128 + lane * 2;
            #pragma unroll
            for (int kx = 0; kx < 3; kx++) {
                const uint32_t* a = ap + kx;
                uint2 b0 = *(const uint2*)(bp + kx * 128);
                uint2 b1 = *(const uint2*)(bp + kx * 128 + 64);
                uint32_t a0 = a[0];
                uint32_t a1 = a[8];
                uint32_t a2 = a[4 * PLANE];
                uint32_t a3 = a[4 * PLANE + 8];
                mma_tf32(c[0][0], a0, a1, a2, a3, b0.x, b0.y);
                mma_tf32(c[0][1], a0, a1, a2, a3, b1.x, b1.y);
                uint32_t a4 = a[16];
                uint32_t a5 = a[24];
                uint32_t a6 = a[4 * PLANE + 16];
                uint32_t a7 = a[4 * PLANE + 24];
                mma_tf32(c[1][0], a4, a5, a6, a7, b0.x, b0.y);
                mma_tf32(c[1][1], a4, a5, a6, a7, b1.x, b1.y);
            }
        }

        if (kc == 1) {
            // epilogue for subtile ph>>1
            const int yo = Y0 + 4 * (ph >> 1) + rr;
            if (yo < OUT_W) {
                float* yn = y + ((size_t)n * 16) * (OUT_W * OUT_W) + (size_t)yo * OUT_W;
                #pragma unroll
                for (int u = 0; u < 2; u++) {
                    int xoA = X0 + q + u * 16 + lm;
                    int xoB = xoA + 8;
                    #pragma unroll
                    for (int h = 0; h < 2; h++) {
                        const float* cc = c[u][h];
                        int coA = h * 8 + lk * 2;
                        float bA = bsm[coA]     - 0.7f;
                        float bB = bsm[coA + 1] - 0.7f;
                        if (xoA < OUT_W) {
                            yn[(size_t)coA       * (OUT_W * OUT_W) + xoA] = mish_f(cc[0] + bA);
                            yn[(size_t)(coA + 1) * (OUT_W * OUT_W) + xoA] = mish_f(cc[1] + bB);
                        }
                        if (xoB < OUT_W) {
                            yn[(size_t)coA       * (OUT_W * OUT_W) + xoB] = mish_f(cc[2] + bA);
                            yn[(size_t)(coA + 1) * (OUT_W * OUT_W) + xoB] = mish_f(cc[3] + bB);
                        }
                    }
                }
            }
        }

        __syncthreads();                  // buffer kc free before refill
        if (ph < 6) LOAD_PH(ph & 1, ph + 2);
    }
}

extern "C" void kernel_launch(void* const* d_in, const int* in_sizes, int n_in,
                              void* d_out, int out_size)
{
    const float* x  = (const float*)d_in[0];
    const float* w  = (const float*)d_in[1];
    const float* b  = (const float*)d_in[2];
    float* y = (float*)d_out;

    cudaFuncSetAttribute(conv_tc_kernel,
                         cudaFuncAttributeMaxDynamicSharedMemorySize, SMEM_BYTES);

    int N = in_sizes[0] / (16 * IN_HW);                 // 32
    dim3 grid(4, 16, N);                                // 4 x 16 x 32 = 2048 CTAs
    conv_tc_kernel<<<grid, 256, SMEM_BYTES>>>(x, w, b, y);
}

// round 11
// speedup vs baseline: 1.5826x; 1.0826x over previous
#include <cuda_runtime.h>
#include <stdint.h>

#define IN_W 256
#define IN_HW 65536
#define OUT_W 254

#define PITCH 68                 // words per staged row (64 + 2 halo + 2 pad)
#define PLANE 408                // 6*PITCH; %32==24 -> lk*PLANE conflict-free
#define BUFW (8 * PLANE)         // 3264 words per stage (8 ci-planes)
#define BF_WORDS 2304
#define SMEM_BYTES ((3 * BUFW + BF_WORDS + 16) * 4)   // 48,448 B -> 3 CTAs/SM

__device__ __forceinline__ uint32_t tf32r(float f) {
    uint32_t r; asm("cvt.rna.tf32.f32 %0, %1;" : "=r"(r) : "f"(f)); return r;
}
__device__ __forceinline__ void mma_tf32(float c[4], uint32_t a0, uint32_t a1,
                                         uint32_t a2, uint32_t a3,
                                         uint32_t b0, uint32_t b1) {
    asm("mma.sync.aligned.m16n8k8.row.col.f32.tf32.tf32.f32 "
        "{%0,%1,%2,%3}, {%4,%5,%6,%7}, {%8,%9}, {%0,%1,%2,%3};"
        : "+f"(c[0]), "+f"(c[1]), "+f"(c[2]), "+f"(c[3])
        : "r"(a0), "r"(a1), "r"(a2), "r"(a3), "r"(b0), "r"(b1));
}
__device__ __forceinline__ float mish_f(float v) {
    if (v > 30.0f) return v;
    float e  = __expf(v);
    float t  = 1.0f + e;
    float t2 = t * t;
    return v * __fdividef(t2 - 1.0f, t2 + 1.0f);
}

__global__ __launch_bounds__(256, 3)
void conv_tc_kernel(const float* __restrict__ x,
                    const float* __restrict__ w,
                    const float* __restrict__ bias,
                    float* __restrict__ y)
{
    extern __shared__ uint32_t sm[];
    uint32_t* stage = sm;                    // 3 half-K stage buffers [ci8][row6][pos68]
    uint32_t* Bf    = sm + 3 * BUFW;
    float*    bsm   = (float*)(sm + 3 * BUFW + BF_WORDS);

    const int tid  = threadIdx.x;
    const int wid  = tid >> 5;
    const int lane = tid & 31;
    const int lm   = lane >> 2;
    const int lk   = lane & 3;
    const int X0   = blockIdx.x * 64;
    const int Y0   = blockIdx.y * 16;
    const int n    = blockIdx.z;

    if (tid < 16) bsm[tid] = bias[tid];

    // ---- B fragments: Bf[(kc*9 + ky*3 + kx)*128 + h*64 + lane*2 + reg]
    for (int i = tid; i < BF_WORDS; i += 256) {
        int reg = i & 1;
        int ln  = (i >> 1) & 31;
        int h   = (i >> 6) & 1;
        int t   = i >> 7;
        int kx  = t % 3;
        int kyc = t / 3;
        int ky  = kyc % 3;
        int kc  = kyc / 3;
        int ci  = kc * 8 + (ln & 3) + reg * 4;
        int co  = h * 8 + (ln >> 2);
        Bf[i] = tf32r(w[(co * 16 + ci) * 9 + ky * 3 + kx]);
    }

    const float* xn = x + (size_t)n * 16 * IN_HW;
    const uint32_t sb = (uint32_t)__cvta_generic_to_shared(stage);

    // ---- precomputed loader slots: 768 body chunks = 3/thread, 48 halo (tid<48)
    int      srow[3];
    uint32_t soff[3];   // element offset: cil*IN_HW + gx
    uint32_t sdst[3];   // byte offset within a stage buffer
    #pragma unroll
    for (int s = 0; s < 3; s++) {
        int j     = tid + 256 * s;
        int pos16 = j & 15;
        int rc    = j >> 4;          // 0..47
        int row   = rc % 6;
        int cil   = rc / 6;
        srow[s] = row;
        soff[s] = (uint32_t)(cil * IN_HW + X0 + pos16 * 4);
        sdst[s] = (uint32_t)((cil * PLANE + row * PITCH + pos16 * 4) * 4);
    }
    int hrow = 0; uint32_t hoff = 0, hdst = 0;
    if (tid < 48) {
        int cil = tid / 6;
        hrow = tid % 6;
        int gx = X0 + 64; if (gx > 252) gx = 252;   // dummy: guarded outputs only
        hoff = (uint32_t)(cil * IN_HW + gx);
        hdst = (uint32_t)((cil * PLANE + hrow * PITCH + 64) * 4);
    }

    // phase ph: subtile ph>>1, ci-half ph&1 -> buffer p
    #define LOAD_PH(p, ph)                                                          \
    do {                                                                            \
        int Ys = Y0 + 4 * ((ph) >> 1);                                              \
        uint32_t cofs = ((ph) & 1) ? (uint32_t)(8 * IN_HW) : 0u;                    \
        uint32_t sbp  = sb + (uint32_t)(p) * (BUFW * 4);                            \
        _Pragma("unroll")                                                           \
        for (int s = 0; s < 3; s++) {                                               \
            int gy = Ys + srow[s]; if (gy > 255) gy = 255;                          \
            const float* src = xn + cofs + soff[s] + gy * IN_W;                     \
            asm volatile("cp.async.cg.shared.global [%0], [%1], 16;"                \
                         :: "r"(sbp + sdst[s]), "l"(src));                          \
        }                                                                           \
        if (tid < 48) {                                                             \
            int gy = Ys + hrow; if (gy > 255) gy = 255;                             \
            const float* src = xn + cofs + hoff + gy * IN_W;                        \
            asm volatile("cp.async.cg.shared.global [%0], [%1], 16;"                \
                         :: "r"(sbp + hdst), "l"(src));                             \
        }                                                                           \
        asm volatile("cp.async.commit_group;");                                     \
    } while (0)

    LOAD_PH(0, 0);
    LOAD_PH(1, 1);

    const int rr = wid >> 1;
    const int q  = (wid & 1) * 32;
    float c[2][2][4];
    int bi = 0;                       // buffer being computed this phase

    #pragma unroll 1
    for (int ph = 0; ph < 8; ph++) {
        if (ph < 7) asm volatile("cp.async.wait_group 1;");
        else        asm volatile("cp.async.wait_group 0;");
        __syncthreads();              // phase data visible; buffer bi+2 free

        if (ph < 6) {
            int li = bi + 2; if (li >= 3) li -= 3;
            LOAD_PH(li, ph + 2);      // overlaps this phase's compute
        }

        const int kc = ph & 1;
        const uint32_t* Ab = stage + bi * BUFW;

        if (kc == 0) {
            #pragma unroll
            for (int u = 0; u < 2; u++)
                #pragma unroll
                for (int h = 0; h < 2; h++)
                    #pragma unroll
                    for (int e = 0; e < 4; e++) c[u][h][e] = 0.f;
        }

        #pragma unroll
        for (int ky = 0; ky < 3; ky++) {
            const uint32_t* ap = Ab + lk * PLANE + (rr + ky) * PITCH + q + lm;
            const uint32_t* bp = Bf + (kc * 9 + ky * 3) * 128 + lane * 2;
            #pragma unroll
            for (int kx = 0; kx < 3; kx++) {
                const uint32_t* a = ap + kx;
                uint2 b0 = *(const uint2*)(bp + kx * 128);
                uint2 b1 = *(const uint2*)(bp + kx * 128 + 64);
                uint32_t a0 = a[0];
                uint32_t a1 = a[8];
                uint32_t a2 = a[4 * PLANE];
                uint32_t a3 = a[4 * PLANE + 8];
                mma_tf32(c[0][0], a0, a1, a2, a3, b0.x, b0.y);
                mma_tf32(c[0][1], a0, a1, a2, a3, b1.x, b1.y);
                uint32_t a4 = a[16];
                uint32_t a5 = a[24];
                uint32_t a6 = a[4 * PLANE + 16];
                uint32_t a7 = a[4 * PLANE + 24];
                mma_tf32(c[1][0], a4, a5, a6, a7, b0.x, b0.y);
                mma_tf32(c[1][1], a4, a5, a6, a7, b1.x, b1.y);
            }
        }

        if (kc == 1) {
            const int yo = Y0 + 4 * (ph >> 1) + rr;
            if (yo < OUT_W) {
                float* yn = y + ((size_t)n * 16) * (OUT_W * OUT_W) + (size_t)yo * OUT_W;
                #pragma unroll
                for (int u = 0; u < 2; u++) {
                    int xoA = X0 + q + u * 16 + lm;
                    int xoB = xoA + 8;
                    #pragma unroll
                    for (int h = 0; h < 2; h++) {
                        const float* cc = c[u][h];
                        int coA = h * 8 + lk * 2;
                        float bA = bsm[coA]     - 0.7f;
                        float bB = bsm[coA + 1] - 0.7f;
                        if (xoA < OUT_W) {
                            yn[(size_t)coA       * (OUT_W * OUT_W) + xoA] = mish_f(cc[0] + bA);
                            yn[(size_t)(coA + 1) * (OUT_W * OUT_W) + xoA] = mish_f(cc[1] + bB);
                        }
                        if (xoB < OUT_W) {
                            yn[(size_t)coA       * (OUT_W * OUT_W) + xoB] = mish_f(cc[2] + bA);
                            yn[(size_t)(coA + 1) * (OUT_W * OUT_W) + xoB] = mish_f(cc[3] + bB);
                        }
                    }
                }
            }
        }

        bi = (bi == 2) ? 0 : bi + 1;
    }
}

extern "C" void kernel_launch(void* const* d_in, const int* in_sizes, int n_in,
                              void* d_out, int out_size)
{
    const float* x  = (const float*)d_in[0];
    const float* w  = (const float*)d_in[1];
    const float* b  = (const float*)d_in[2];
    float* y = (float*)d_out;

    cudaFuncSetAttribute(conv_tc_kernel,
                         cudaFuncAttributeMaxDynamicSharedMemorySize, SMEM_BYTES);

    int N = in_sizes[0] / (16 * IN_HW);                 // 32
    dim3 grid(4, 16, N);                                // 2048 CTAs
    conv_tc_kernel<<<grid, 256, SMEM_BYTES>>>(x, w, b, y);
}